// round 10
// baseline (speedup 1.0000x reference)
#include <cuda_runtime.h>
#include <cstdint>

// AtomDistances: out[b,a,n] = mask ? || pos[nbr[b,a,n]] - pos[b,a] + cell_offsets[b,a,n,:] @ cell[b] || : 0
// B=16, A=4096, N=128. dtypes (harness): neighbors int32, mask int32.
//
// R8: occupancy attack. R7 was latency-bound (DRAM 67%, L1 60%, issue 39%, occ 45%):
// 256-thr blocks cap at 32 warps/SM because each 48 KB smem position copy serves
// only 8 warps. Now: 512-thr blocks, launch_bounds(512,3) -> <=42 regs,
// 3 blocks/SM x 16 warps = 48 warps (75% occ), smem 3x48=144 KB.
// Grid = exactly one balanced wave: 444 blocks (12 batches x 28 + 4 x 27).
// div/mod by groups-per-atom replaced with shift/mask; 32-bit indexing.

#define THREADS 512

__global__ void __launch_bounds__(THREADS, 3) atom_distances_kernel(
    const float* __restrict__ pos,    // (B, A, 3)
    const int*   __restrict__ nbr,    // (B, A, N) int32
    const float* __restrict__ cell,   // (B, 3, 3)
    const float* __restrict__ coff,   // (B, A, N, 3)
    const int*   __restrict__ mask,   // (B, A, N) int32 (0/1)
    float*       __restrict__ out,    // (B, A, N)
    int A, int N,
    int ngShift,                      // log2(N/4)
    int split, int blkHi, int blkLo)  // batch->block partition (balanced wave)
{
    __shared__ float4 s_pos4[3072];                  // 48 KB = A*3 floats (A=4096)
    float* s_pos = reinterpret_cast<float*>(s_pos4);

    const int tid = threadIdx.x;

    // ---- map 1D block id -> (batch b, block-within-batch j, nblk) ----
    int bid = blockIdx.x;
    int b, j, nblk;
    int hiTotal = split * blkHi;
    if (bid < hiTotal) { b = bid / blkHi; j = bid - b * blkHi; nblk = blkHi; }
    else {
        int t = bid - hiTotal;
        int bb = t / blkLo;
        b = split + bb; j = t - bb * blkLo; nblk = blkLo;
    }

    // ---- stage this batch's positions into smem ----
    const float4* pb4 = reinterpret_cast<const float4*>(pos + (size_t)b * A * 3);
    const int n_vec4 = (A * 3) >> 2;                 // 3072
    for (int i = tid; i < n_vec4; i += THREADS)
        s_pos4[i] = pb4[i];

    // ---- cell matrix for this batch (L1-resident, uniform address) ----
    const float* C = cell + b * 9;
    float c00 = __ldg(C+0), c01 = __ldg(C+1), c02 = __ldg(C+2);
    float c10 = __ldg(C+3), c11 = __ldg(C+4), c12 = __ldg(C+5);
    float c20 = __ldg(C+6), c21 = __ldg(C+7), c22 = __ldg(C+8);

    __syncthreads();

    const int ngMask = (1 << ngShift) - 1;           // N/4 - 1
    const int groups_per_batch = A << ngShift;       // 131072
    const int chunk = (groups_per_batch + nblk - 1) / nblk;
    const int start = j * chunk;
    const int end   = min(start + chunk, groups_per_batch);

    const int bbase = b * A * N;                     // < 2^23, int-safe

    for (int gl = start + tid; gl < end; gl += THREADS) {
        int a    = gl >> ngShift;
        int n4   = gl & ngMask;
        int base = bbase + a * N + (n4 << 2);        // element index, int-safe

        // --- front-batched wide streaming loads (MLP) ---
        int4 nb4 = *reinterpret_cast<const int4*>(nbr + base);
        const float4* co4 = reinterpret_cast<const float4*>(coff + (size_t)base * 3);
        float4 q0 = co4[0];
        float4 q1 = co4[1];
        float4 q2 = co4[2];
        int4 m4 = *reinterpret_cast<const int4*>(mask + base);

        // central atom position (smem broadcast across 8 threads/atom)
        float ax = s_pos[a*3 + 0], ay = s_pos[a*3 + 1], az = s_pos[a*3 + 2];

        int n0 = min(max(nb4.x, 0), A - 1) * 3;      // defensive clamp + stride 3
        int n1 = min(max(nb4.y, 0), A - 1) * 3;
        int n2 = min(max(nb4.z, 0), A - 1) * 3;
        int n3 = min(max(nb4.w, 0), A - 1) * 3;

        float res0, res1, res2, res3;
        {
            float px = s_pos[n0+0], py = s_pos[n0+1], pz = s_pos[n0+2];
            float ox = fmaf(q0.x, c00, fmaf(q0.y, c10, q0.z * c20));
            float oy = fmaf(q0.x, c01, fmaf(q0.y, c11, q0.z * c21));
            float oz = fmaf(q0.x, c02, fmaf(q0.y, c12, q0.z * c22));
            float dx = px - ax + ox, dy = py - ay + oy, dz = pz - az + oz;
            res0 = m4.x ? sqrtf(fmaf(dx, dx, fmaf(dy, dy, dz * dz))) : 0.0f;
        }
        {
            float px = s_pos[n1+0], py = s_pos[n1+1], pz = s_pos[n1+2];
            float ox = fmaf(q0.w, c00, fmaf(q1.x, c10, q1.y * c20));
            float oy = fmaf(q0.w, c01, fmaf(q1.x, c11, q1.y * c21));
            float oz = fmaf(q0.w, c02, fmaf(q1.x, c12, q1.y * c22));
            float dx = px - ax + ox, dy = py - ay + oy, dz = pz - az + oz;
            res1 = m4.y ? sqrtf(fmaf(dx, dx, fmaf(dy, dy, dz * dz))) : 0.0f;
        }
        {
            float px = s_pos[n2+0], py = s_pos[n2+1], pz = s_pos[n2+2];
            float ox = fmaf(q1.z, c00, fmaf(q1.w, c10, q2.x * c20));
            float oy = fmaf(q1.z, c01, fmaf(q1.w, c11, q2.x * c21));
            float oz = fmaf(q1.z, c02, fmaf(q1.w, c12, q2.x * c22));
            float dx = px - ax + ox, dy = py - ay + oy, dz = pz - az + oz;
            res2 = m4.z ? sqrtf(fmaf(dx, dx, fmaf(dy, dy, dz * dz))) : 0.0f;
        }
        {
            float px = s_pos[n3+0], py = s_pos[n3+1], pz = s_pos[n3+2];
            float ox = fmaf(q2.y, c00, fmaf(q2.z, c10, q2.w * c20));
            float oy = fmaf(q2.y, c01, fmaf(q2.z, c11, q2.w * c21));
            float oz = fmaf(q2.y, c02, fmaf(q2.z, c12, q2.w * c22));
            float dx = px - ax + ox, dy = py - ay + oy, dz = pz - az + oz;
            res3 = m4.w ? sqrtf(fmaf(dx, dx, fmaf(dy, dy, dz * dz))) : 0.0f;
        }

        *reinterpret_cast<float4*>(out + base) = make_float4(res0, res1, res2, res3);
    }
}

extern "C" void kernel_launch(void* const* d_in, const int* in_sizes, int n_in,
                              void* d_out, int out_size)
{
    const float* pos  = (const float*)d_in[0];   // (B,A,3)
    const int*   nbr  = (const int*)d_in[1];     // (B,A,N) int32
    const float* cell = (const float*)d_in[2];   // (B,3,3)
    const float* coff = (const float*)d_in[3];   // (B,A,N,3)
    const int*   mask = (const int*)d_in[4];     // (B,A,N) int32

    int B = in_sizes[2] / 9;
    int A = in_sizes[0] / (3 * B);
    int N = in_sizes[1] / (B * A);

    int ng = N >> 2;                  // groups per atom (power of 2: 32)
    int ngShift = 0;
    while ((1 << ngShift) < ng) ngShift++;

    // Exactly one balanced wave: 148 SMs x 3 blocks = 444 blocks.
    int total_blocks = 444;
    int blkLo = total_blocks / B;                 // 27
    int split = total_blocks - blkLo * B;         // first `split` batches get blkLo+1
    int blkHi = blkLo + 1;                        // 28

    atom_distances_kernel<<<total_blocks, THREADS>>>(
        pos, nbr, cell, coff, mask, (float*)d_out,
        A, N, ngShift, split, blkHi, blkLo);
}

// round 13
// speedup vs baseline: 1.0156x; 1.0156x over previous
#include <cuda_runtime.h>
#include <cstdint>

// AtomDistances: out[b,a,n] = mask ? || pos[nbr[b,a,n]] - pos[b,a] + cell_offsets[b,a,n,:] @ cell[b] || : 0
// B=16, A=4096, N=128. dtypes (harness): neighbors int32, mask int32.
//
// R10: revert to R7 config (256 thr, 48 KB smem, 4 blocks/SM, 592-block single
// wave) -- the R8 occupancy push (48 warps/SM) LOWERED DRAM% -> kernel is
// per-thread-MLP-bound, not warp-bound. This round doubles per-thread work to
// 8 neighbors: 10 front-batched wide LDGs/thread (2 int4 nbr + 6 float4 coff +
// 2 int4 mask), halved loop overhead, central atom + cell amortized over 8.

#define THREADS 256

__device__ __forceinline__ float dist1(
    const float* __restrict__ s_pos, int ni, int mm,
    float cox, float coy, float coz,
    float ax, float ay, float az,
    float c00, float c01, float c02,
    float c10, float c11, float c12,
    float c20, float c21, float c22)
{
    int p = ni * 3;                                  // stride 3: coprime w/ 32 banks
    float px = s_pos[p + 0];
    float py = s_pos[p + 1];
    float pz = s_pos[p + 2];
    float ox = fmaf(cox, c00, fmaf(coy, c10, coz * c20));
    float oy = fmaf(cox, c01, fmaf(coy, c11, coz * c21));
    float oz = fmaf(cox, c02, fmaf(coy, c12, coz * c22));
    float dx = px - ax + ox;
    float dy = py - ay + oy;
    float dz = pz - az + oz;
    float d  = sqrtf(fmaf(dx, dx, fmaf(dy, dy, dz * dz)));
    return mm ? d : 0.0f;
}

__global__ void __launch_bounds__(THREADS, 4) atom_distances_kernel(
    const float* __restrict__ pos,    // (B, A, 3)
    const int*   __restrict__ nbr,    // (B, A, N) int32
    const float* __restrict__ cell,   // (B, 3, 3)
    const float* __restrict__ coff,   // (B, A, N, 3)
    const int*   __restrict__ mask,   // (B, A, N) int32 (0/1)
    float*       __restrict__ out,    // (B, A, N)
    int A, int N, int ng8Shift)       // ng8Shift = log2(N/8)
{
    __shared__ float4 s_pos4[3072];                  // 48 KB = A*3 floats (A=4096)
    float* s_pos = reinterpret_cast<float*>(s_pos4);

    const int b   = blockIdx.y;
    const int tid = threadIdx.x;

    // ---- stage this batch's positions into smem ----
    const float4* pb4 = reinterpret_cast<const float4*>(pos + (size_t)b * A * 3);
    const int n_vec4 = (A * 3) >> 2;                 // 3072
#pragma unroll 4
    for (int i = tid; i < n_vec4; i += THREADS)
        s_pos4[i] = pb4[i];

    // ---- cell matrix for this batch (L1-resident) ----
    const float* C = cell + b * 9;
    float c00 = __ldg(C+0), c01 = __ldg(C+1), c02 = __ldg(C+2);
    float c10 = __ldg(C+3), c11 = __ldg(C+4), c12 = __ldg(C+5);
    float c20 = __ldg(C+6), c21 = __ldg(C+7), c22 = __ldg(C+8);

    __syncthreads();

    const int ng8Mask = (1 << ng8Shift) - 1;         // N/8 - 1
    const int groups_per_batch = A << ng8Shift;      // 65536
    const int chunk = (groups_per_batch + gridDim.x - 1) / gridDim.x;
    const int start = blockIdx.x * chunk;
    const int end   = min(start + chunk, groups_per_batch);

    const int bbase = b * A * N;                     // < 2^23, int-safe
    const int Am1   = A - 1;

    for (int gl = start + tid; gl < end; gl += THREADS) {
        int a    = gl >> ng8Shift;
        int n8   = gl & ng8Mask;
        int base = bbase + a * N + (n8 << 3);        // first of 8 elements

        // --- front-batched wide streaming loads: 10 in flight ---
        int4 nbA = *reinterpret_cast<const int4*>(nbr + base);
        int4 nbB = *reinterpret_cast<const int4*>(nbr + base + 4);
        const float4* co4 = reinterpret_cast<const float4*>(coff + (size_t)base * 3);
        float4 q0 = co4[0];
        float4 q1 = co4[1];
        float4 q2 = co4[2];
        float4 q3 = co4[3];
        float4 q4 = co4[4];
        float4 q5 = co4[5];
        int4 mA = *reinterpret_cast<const int4*>(mask + base);
        int4 mB = *reinterpret_cast<const int4*>(mask + base + 4);

        // central atom position (smem broadcast across 16 threads/atom)
        float ax = s_pos[a*3 + 0], ay = s_pos[a*3 + 1], az = s_pos[a*3 + 2];

        int i0 = min(max(nbA.x, 0), Am1);
        int i1 = min(max(nbA.y, 0), Am1);
        int i2 = min(max(nbA.z, 0), Am1);
        int i3 = min(max(nbA.w, 0), Am1);
        int i4 = min(max(nbB.x, 0), Am1);
        int i5 = min(max(nbB.y, 0), Am1);
        int i6 = min(max(nbB.z, 0), Am1);
        int i7 = min(max(nbB.w, 0), Am1);

        float r0 = dist1(s_pos, i0, mA.x, q0.x, q0.y, q0.z, ax, ay, az,
                         c00,c01,c02,c10,c11,c12,c20,c21,c22);
        float r1 = dist1(s_pos, i1, mA.y, q0.w, q1.x, q1.y, ax, ay, az,
                         c00,c01,c02,c10,c11,c12,c20,c21,c22);
        float r2 = dist1(s_pos, i2, mA.z, q1.z, q1.w, q2.x, ax, ay, az,
                         c00,c01,c02,c10,c11,c12,c20,c21,c22);
        float r3 = dist1(s_pos, i3, mA.w, q2.y, q2.z, q2.w, ax, ay, az,
                         c00,c01,c02,c10,c11,c12,c20,c21,c22);
        *reinterpret_cast<float4*>(out + base) = make_float4(r0, r1, r2, r3);

        float r4 = dist1(s_pos, i4, mB.x, q3.x, q3.y, q3.z, ax, ay, az,
                         c00,c01,c02,c10,c11,c12,c20,c21,c22);
        float r5 = dist1(s_pos, i5, mB.y, q3.w, q4.x, q4.y, ax, ay, az,
                         c00,c01,c02,c10,c11,c12,c20,c21,c22);
        float r6 = dist1(s_pos, i6, mB.z, q4.z, q4.w, q5.x, ax, ay, az,
                         c00,c01,c02,c10,c11,c12,c20,c21,c22);
        float r7 = dist1(s_pos, i7, mB.w, q5.y, q5.z, q5.w, ax, ay, az,
                         c00,c01,c02,c10,c11,c12,c20,c21,c22);
        *reinterpret_cast<float4*>(out + base + 4) = make_float4(r4, r5, r6, r7);
    }
}

extern "C" void kernel_launch(void* const* d_in, const int* in_sizes, int n_in,
                              void* d_out, int out_size)
{
    const float* pos  = (const float*)d_in[0];   // (B,A,3)
    const int*   nbr  = (const int*)d_in[1];     // (B,A,N) int32
    const float* cell = (const float*)d_in[2];   // (B,3,3)
    const float* coff = (const float*)d_in[3];   // (B,A,N,3)
    const int*   mask = (const int*)d_in[4];     // (B,A,N) int32

    int B = in_sizes[2] / 9;
    int A = in_sizes[0] / (3 * B);
    int N = in_sizes[1] / (B * A);

    int ng8 = N >> 3;                 // 8-neighbor groups per atom (16)
    int ng8Shift = 0;
    while ((1 << ng8Shift) < ng8) ng8Shift++;

    // 37 x 16 = 592 blocks = 148 SMs x 4 blocks (48 KB smem each): one full wave.
    dim3 grid(37, B, 1);
    atom_distances_kernel<<<grid, THREADS>>>(
        pos, nbr, cell, coff, mask, (float*)d_out, A, N, ng8Shift);
}